// round 14
// baseline (speedup 1.0000x reference)
#include <cuda_runtime.h>
#include <cuda_fp16.h>
#include <math.h>
#include <stdint.h>

#define NN 8192
#define FIN 256
#define FOUT 64
#define LRALPHA 0.2f

#define BM 128
#define BK 64
#define NB 80               // B n-rows: 64 out + ones(64) + zeros(65..79)
#define ASTR 72             // A SMEM stride (halves)
#define BSTR 72             // B SMEM stride (halves)
#define NSPLIT 4
#define JCHUNK (NN / NSPLIT)        // 2048
#define NTILES (JCHUNK / BK)        // 32
#define PART_STRIDE 72

// ---- persistent scratch (no allocations allowed) ----
__device__ __align__(16) __half g_Wht[(size_t)NB * NN];   // transposed fp16 Wh + ones/zeros
__device__ __align__(16) float4 g_rowc[NN];  // (f1, exp(f1-m), exp(.2f1-m), 0)
__device__ __align__(16) float g_cpl[3 * NN]; // planar: [f2][exp(f2)][exp(.2f2)]
__device__ float g_f1[NN];
__device__ float g_f2[NN];
__device__ unsigned int g_m2key = 0u;        // reset by fused reducer (prev replay)
__device__ __align__(16) float g_part[(size_t)NSPLIT * NN * PART_STRIDE];
__device__ int g_cnt[NN / BM];               // per-i-block arrival counters (zero-init)

__device__ __forceinline__ float elu_f(float x) {
    return x > 0.f ? x : expm1f(x);
}
__device__ __forceinline__ unsigned int fkey(float x) {
    unsigned int b = __float_as_uint(x);
    return (b & 0x80000000u) ? ~b : (b | 0x80000000u);
}
__device__ __forceinline__ float fdecode(unsigned int k) {
    return __uint_as_float((k & 0x80000000u) ? (k & 0x7fffffffu) : ~k);
}
__device__ __forceinline__ void cp_async16(uint32_t smem_addr, const void* gptr) {
    asm volatile("cp.async.cg.shared.global [%0], [%1], 16;\n"
                 :: "r"(smem_addr), "l"(gptr));
}
__device__ __forceinline__ void cp_commit() {
    asm volatile("cp.async.commit_group;\n" ::: "memory");
}
__device__ __forceinline__ void cp_wait1() {
    asm volatile("cp.async.wait_group 1;\n" ::: "memory");
}
__device__ __forceinline__ void cp_wait0() {
    asm volatile("cp.async.wait_group 0;\n" ::: "memory");
}
__device__ __forceinline__ void ldsm_x4(uint32_t& r0, uint32_t& r1,
                                        uint32_t& r2, uint32_t& r3, uint32_t a) {
    asm volatile("ldmatrix.sync.aligned.m8n8.x4.shared.b16 {%0,%1,%2,%3}, [%4];"
                 : "=r"(r0), "=r"(r1), "=r"(r2), "=r"(r3) : "r"(a));
}
__device__ __forceinline__ void ldsm_x2(uint32_t& r0, uint32_t& r1, uint32_t a) {
    asm volatile("ldmatrix.sync.aligned.m8n8.x2.shared.b16 {%0,%1}, [%2];"
                 : "=r"(r0), "=r"(r1) : "r"(a));
}

// ---------------------------------------------------------------------------
// Kernel 1: Wh = h @ W (fp32), transposed fp16 store; fused f1/f2 + M2.
// (R13 version, unchanged.)
// ---------------------------------------------------------------------------
__global__ __launch_bounds__(256) void k_gemm_wh(
    const float* __restrict__ h, const float* __restrict__ W,
    const float* __restrict__ a)
{
    __shared__ float hs[64][68];
    __shared__ float wt2[64][68];
    __shared__ unsigned int smax;
    float* ts = &hs[0][0];         // alias: transpose staging [c][r], stride 65

    int t = threadIdx.x;
    int i0 = blockIdx.x * 64;
    int cg = t & 15;               // col-group: cols 4cg..4cg+3
    int rs = t >> 4;               // row-slot : rows 4rs..4rs+3

    if (t == 0) smax = 0u;

    float4 acc[4];
#pragma unroll
    for (int q = 0; q < 4; q++) acc[q] = make_float4(0.f, 0.f, 0.f, 0.f);

    for (int kt = 0; kt < FIN; kt += 64) {
        __syncthreads();
#pragma unroll
        for (int it = 0; it < 16; it++) {
            int l = t + 256 * it;
            int r = l >> 6, c = l & 63;
            hs[r][c]  = h[(size_t)(i0 + r) * FIN + kt + c];
            wt2[r][c] = W[(size_t)(kt + r) * FOUT + c];
        }
        __syncthreads();
#pragma unroll
        for (int k4 = 0; k4 < 16; k4++) {
            float4 w0 = *(const float4*)&wt2[k4 * 4 + 0][cg * 4];
            float4 w1 = *(const float4*)&wt2[k4 * 4 + 1][cg * 4];
            float4 w2 = *(const float4*)&wt2[k4 * 4 + 2][cg * 4];
            float4 w3 = *(const float4*)&wt2[k4 * 4 + 3][cg * 4];
#pragma unroll
            for (int q = 0; q < 4; q++) {
                float4 hv = *(const float4*)&hs[rs * 4 + q][k4 * 4];  // broadcast
                acc[q].x += hv.x * w0.x + hv.y * w1.x + hv.z * w2.x + hv.w * w3.x;
                acc[q].y += hv.x * w0.y + hv.y * w1.y + hv.z * w2.y + hv.w * w3.y;
                acc[q].z += hv.x * w0.z + hv.y * w1.z + hv.z * w2.z + hv.w * w3.z;
                acc[q].w += hv.x * w0.w + hv.y * w1.w + hv.z * w2.w + hv.w * w3.w;
            }
        }
    }

    // ---- fused f1/f2: per-row dots with a1/a2, reduce across the 16 cg lanes
    {
        float4 a1v = *(const float4*)&a[4 * cg];
        float4 a2v = *(const float4*)&a[64 + 4 * cg];
        float s1[4], s2[4];
#pragma unroll
        for (int q = 0; q < 4; q++) {
            s1[q] = acc[q].x * a1v.x + acc[q].y * a1v.y
                  + acc[q].z * a1v.z + acc[q].w * a1v.w;
            s2[q] = acc[q].x * a2v.x + acc[q].y * a2v.y
                  + acc[q].z * a2v.z + acc[q].w * a2v.w;
        }
#pragma unroll
        for (int o = 8; o > 0; o >>= 1) {
#pragma unroll
            for (int q = 0; q < 4; q++) {
                s1[q] += __shfl_xor_sync(0xffffffffu, s1[q], o);
                s2[q] += __shfl_xor_sync(0xffffffffu, s2[q], o);
            }
        }
        if (cg == 0) {
            float mm = -1e30f;
#pragma unroll
            for (int q = 0; q < 4; q++) {
                g_f1[i0 + rs * 4 + q] = s1[q];
                g_f2[i0 + rs * 4 + q] = s2[q];
                mm = fmaxf(mm, s2[q]);
            }
            atomicMax(&smax, fkey(mm));
        }
    }
    __syncthreads();               // hs free; smax complete
    if (t == 0) atomicMax(&g_m2key, smax);

    // ---- stage transpose ts[c][r] (stride 65), then fp16 write
#pragma unroll
    for (int q = 0; q < 4; q++) {
        ts[(4 * cg + 0) * 65 + rs * 4 + q] = acc[q].x;
        ts[(4 * cg + 1) * 65 + rs * 4 + q] = acc[q].y;
        ts[(4 * cg + 2) * 65 + rs * 4 + q] = acc[q].z;
        ts[(4 * cg + 3) * 65 + rs * 4 + q] = acc[q].w;
    }
    __syncthreads();
    {
        int c2 = t >> 2, q = t & 3;        // c2: col 0..63, q: 16-row chunk
        __half2 hx[8];
#pragma unroll
        for (int j = 0; j < 8; j++)
            hx[j] = __floats2half2_rn(ts[c2 * 65 + q * 16 + 2 * j],
                                      ts[c2 * 65 + q * 16 + 2 * j + 1]);
        float4* dst = (float4*)&g_Wht[(size_t)c2 * NN + i0 + q * 16];
        dst[0] = *(float4*)&hx[0];
        dst[1] = *(float4*)&hx[4];
    }
    // ones / zero rows 64..79 for this i-slice (4 halves per thread)
    {
        int rz = 64 + (t >> 4), ii = (t & 15) * 4;
        __half v = (rz == 64) ? __float2half(1.0f) : __float2half(0.0f);
        __half2 vv = __halves2half2(v, v);
        *(__half2*)&g_Wht[(size_t)rz * NN + i0 + ii] = vv;
        *(__half2*)&g_Wht[(size_t)rz * NN + i0 + ii + 2] = vv;
    }
}

// ---------------------------------------------------------------------------
// Kernel 2: row constants (AoS) + column constants (planar).  (Unchanged.)
// ---------------------------------------------------------------------------
__global__ __launch_bounds__(256) void k_consts()
{
    int i = blockIdx.x * 256 + threadIdx.x;
    float M2 = fdecode(g_m2key);
    float f1 = g_f1[i], f2 = g_f2[i];
    float z = f1 + M2;
    float m = (z > 0.f) ? z : LRALPHA * z;
    g_rowc[i] = make_float4(f1, expf(f1 - m), expf(LRALPHA * f1 - m), 0.f);
    g_cpl[i]          = f2;
    g_cpl[NN + i]     = expf(f2);
    g_cpl[2 * NN + i] = expf(LRALPHA * f2);
}

// ---------------------------------------------------------------------------
// Kernel 3: fused masked-softmax attention partials + FUSED final reduce.
// Changes vs R13:
//  (a) B/colc triple-buffered ring -> 2 syncs/tile (cp issue for tile tt+2
//      targets buf (tt+2)%3, disjoint from MMA(tt) and MMA(tt-1) buffers, so
//      it moves after w-gen and the third barrier disappears).  cp_wait lag
//      grows to ~2 tiles (pending at tile top = {B(tt), B(tt+1)}).
//  (b) last-arriving CTA per i-block reduces partials + elu + writes out
//      (threadFenceReduction pattern; deletes the k_reduce launch).
// SMEM (bytes):
//   [0,     18432)  half  A[128][72]
//   [18432, 52992)  half  B[3][80][72]
//   [52992, 55296)  float colc[3][3][64]   (planar)
//   [55296, 57344)  float4 rowcs[128]
// ---------------------------------------------------------------------------
#define SM_A     0
#define SM_B     18432
#define SM_COLC  52992
#define SM_ROWC  55296
#define SMEM_TOTAL 57344
#define BBUF (NB * BSTR * 2)       // 11520

__global__ __launch_bounds__(256, 2) void k_gat(const int* __restrict__ adj,
                                                float* __restrict__ out)
{
    extern __shared__ __align__(16) char smem[];
    uint32_t sbase = (uint32_t)__cvta_generic_to_shared(smem);
    __shared__ int s_last;

    int t = threadIdx.x;
    int warp = t >> 5, lane = t & 31;
    int ib = blockIdx.x >> 2;
    int i0 = ib * BM;
    int split = blockIdx.x & 3;
    int jstart = split * JCHUNK;

    // fixed row constants for the whole CTA
    if (t < 128) ((float4*)(smem + SM_ROWC))[t] = g_rowc[i0 + t];

    // w-gen mapping: warp -> rows 16w..16w+15; lane: rp = l>>4 row parity,
    // cq = l&15 -> cols 4cq..4cq+3.  Thread rows: wrow0 + rp + 2k, k=0..7.
    int wrow0 = warp * 16;
    int rp = lane >> 4;
    int cq = lane & 15;
    const int* aptr = adj + (size_t)(i0 + wrow0 + rp) * NN + 4 * cq;

    // MMA mapping
    int mb = (warp & 3) * 32;      // 32 rows (2 m-tiles)
    int nb = (warp >> 2) * 40;     // 40 cols (5 n-tiles)
    int g = lane >> 2, tig = lane & 3;

    // ldmatrix lane addresses
    uint32_t a_ad0 = sbase + SM_A +
        (uint32_t)(((mb + (lane & 15)) * ASTR + ((lane >> 4) << 3)) * 2);
    uint32_t a_ad1 = a_ad0 + 16 * ASTR * 2;
    uint32_t b_off_p = (uint32_t)(((nb + ((lane >> 4) << 3) + (lane & 7)) * BSTR
                                   + (((lane >> 3) & 1) << 3)) * 2);
    uint32_t b_off_2 = (uint32_t)(((nb + 32 + (lane & 7)) * BSTR
                                   + (((lane >> 3) & 1) << 3)) * 2);

    float acc[2][5][4];
#pragma unroll
    for (int m = 0; m < 2; m++)
#pragma unroll
        for (int n = 0; n < 5; n++)
#pragma unroll
            for (int x = 0; x < 4; x++) acc[m][n][x] = 0.f;

    // ---- prologue: B(0)/colc(0) -> buf0, B(1)/colc(1) -> buf1; adj(0) regs
#pragma unroll
    for (int pb = 0; pb < 2; pb++) {
        int jp = jstart + pb * BK;
        uint32_t bd = sbase + SM_B + (uint32_t)pb * BBUF;
        uint32_t cd = sbase + SM_COLC + (uint32_t)pb * 768;
#pragma unroll
        for (int it = 0; it < 3; it++) {
            int l = t + 256 * it;
            if (l < 640) {
                int n = l >> 3, kc = l & 7;
                cp_async16(bd + (uint32_t)(n * (BSTR * 2) + kc * 16),
                           &g_Wht[(size_t)n * NN + jp + kc * 8]);
            }
        }
        if (t < 48) {
            int p = t >> 4, x = t & 15;
            cp_async16(cd + (uint32_t)(p * 256 + x * 16),
                       &g_cpl[(size_t)p * NN + jp + x * 4]);
        }
        cp_commit();
    }

    int4 av[8];
#pragma unroll
    for (int k = 0; k < 8; k++)
        av[k] = __ldcs((const int4*)(aptr + (size_t)(2 * k) * NN + jstart));

    int bufB = 0;                  // = tt % 3
    for (int tt = 0; tt < NTILES; tt++) {
        int j0 = jstart + tt * BK;

        // 1. B(tt)/colc(tt) complete (committed 2 tiles ago -> never blocks)
        if (tt + 1 < NTILES) cp_wait1();
        else                 cp_wait0();

        // 2. one barrier: B(tt) visible + MMA(tt-1) drained (A and ring free)
        __syncthreads();

        // 3. w-gen: registers(adj int4) + planar colc + rowc -> fp16 A[128][64]
        {
            const float* cp0 = (const float*)(smem + SM_COLC + bufB * 768);
            float4 f2v = *(const float4*)(cp0 + 4 * cq);
            float4 yv  = *(const float4*)(cp0 + 64 + 4 * cq);
            float4 zv  = *(const float4*)(cp0 + 128 + 4 * cq);
            const float4* rw = (const float4*)(smem + SM_ROWC) + wrow0;
            __half* Ah = (__half*)(smem + SM_A);
#pragma unroll
            for (int k = 0; k < 8; k++) {
                int row = rp + 2 * k;
                float4 rc = rw[row];               // LDS 2-way broadcast
                int4 a4 = av[k];
                float w0 = ((rc.x + f2v.x) > 0.f) ? rc.y * yv.x : rc.z * zv.x;
                float w1 = ((rc.x + f2v.y) > 0.f) ? rc.y * yv.y : rc.z * zv.y;
                float w2 = ((rc.x + f2v.z) > 0.f) ? rc.y * yv.z : rc.z * zv.z;
                float w3 = ((rc.x + f2v.w) > 0.f) ? rc.y * yv.w : rc.z * zv.w;
                w0 = a4.x ? w0 : 0.f;
                w1 = a4.y ? w1 : 0.f;
                w2 = a4.z ? w2 : 0.f;
                w3 = a4.w ? w3 : 0.f;
                __half2 p0 = __floats2half2_rn(w0, w1);
                __half2 p1 = __floats2half2_rn(w2, w3);
                uint2 pk;
                pk.x = *(uint32_t*)&p0;
                pk.y = *(uint32_t*)&p1;
                *(uint2*)&Ah[(wrow0 + row) * ASTR + 4 * cq] = pk;   // STS.64
            }
        }

        // 4. stream adj(tt+1) into registers (flies over sync + MMA)
        if (tt + 1 < NTILES) {
            int jn = j0 + BK;
#pragma unroll
            for (int k = 0; k < 8; k++)
                av[k] = __ldcs((const int4*)(aptr + (size_t)(2 * k) * NN + jn));
        }

        // 5. issue B(tt+2)/colc(tt+2) into buf (tt+2)%3 (free: MMA(tt-1) done)
        if (tt + 2 < NTILES) {
            int jn = j0 + 2 * BK;
            int bufI = (bufB == 0) ? 2 : bufB - 1;   // (tt+2)%3
            uint32_t bd = sbase + SM_B + (uint32_t)bufI * BBUF;
            uint32_t cd = sbase + SM_COLC + (uint32_t)bufI * 768;
#pragma unroll
            for (int it = 0; it < 3; it++) {
                int l = t + 256 * it;
                if (l < 640) {
                    int n = l >> 3, kc = l & 7;
                    cp_async16(bd + (uint32_t)(n * (BSTR * 2) + kc * 16),
                               &g_Wht[(size_t)n * NN + jn + kc * 8]);
                }
            }
            if (t < 48) {
                int p = t >> 4, x = t & 15;
                cp_async16(cd + (uint32_t)(p * 256 + x * 16),
                           &g_cpl[(size_t)p * NN + jn + x * 4]);
            }
            cp_commit();
        }

        // 6. A visible
        __syncthreads();

        // 7. MMA: 4 k-steps x (2 m-tiles x 5 n-tiles), ldmatrix fragments
        uint32_t b_base = sbase + SM_B + (uint32_t)bufB * BBUF;
#pragma unroll
        for (int kt = 0; kt < 4; kt++) {
            uint32_t koff = (uint32_t)kt * 32;    // 16 halves
            uint32_t a0[4], a1[4], bb[10];
            ldsm_x4(a0[0], a0[1], a0[2], a0[3], a_ad0 + koff);
            ldsm_x4(a1[0], a1[1], a1[2], a1[3], a_ad1 + koff);
            ldsm_x4(bb[0], bb[1], bb[2], bb[3], b_base + b_off_p + koff);
            ldsm_x4(bb[4], bb[5], bb[6], bb[7],
                    b_base + b_off_p + 16 * BSTR * 2 + koff);
            ldsm_x2(bb[8], bb[9], b_base + b_off_2 + koff);
#pragma unroll
            for (int nt = 0; nt < 5; nt++) {
                uint32_t b0 = bb[2 * nt], b1 = bb[2 * nt + 1];
                asm volatile(
                    "mma.sync.aligned.m16n8k16.row.col.f32.f16.f16.f32 "
                    "{%0,%1,%2,%3}, {%4,%5,%6,%7}, {%8,%9}, {%0,%1,%2,%3};\n"
                    : "+f"(acc[0][nt][0]), "+f"(acc[0][nt][1]),
                      "+f"(acc[0][nt][2]), "+f"(acc[0][nt][3])
                    : "r"(a0[0]), "r"(a0[1]), "r"(a0[2]), "r"(a0[3]),
                      "r"(b0), "r"(b1));
                asm volatile(
                    "mma.sync.aligned.m16n8k16.row.col.f32.f16.f16.f32 "
                    "{%0,%1,%2,%3}, {%4,%5,%6,%7}, {%8,%9}, {%0,%1,%2,%3};\n"
                    : "+f"(acc[1][nt][0]), "+f"(acc[1][nt][1]),
                      "+f"(acc[1][nt][2]), "+f"(acc[1][nt][3])
                    : "r"(a1[0]), "r"(a1[1]), "r"(a1[2]), "r"(a1[3]),
                      "r"(b0), "r"(b1));
            }
        }

        bufB = (bufB == 2) ? 0 : bufB + 1;
    }

    // ---- write partials: nums (cols 0..63) + den (logical col 64)
    float* pp = &g_part[((size_t)split * NN + i0) * PART_STRIDE];
#pragma unroll
    for (int m = 0; m < 2; m++) {
        int r0 = mb + m * 16 + g, r1 = r0 + 8;
#pragma unroll
        for (int nt = 0; nt < 5; nt++) {
            int nb2 = nb + nt * 8 + 2 * tig;
            if (nb2 < 64) {
                pp[(size_t)r0 * PART_STRIDE + nb2] = acc[m][nt][0];
                pp[(size_t)r1 * PART_STRIDE + nb2] = acc[m][nt][2];
            }
            if (nb2 + 1 < 64) {
                pp[(size_t)r0 * PART_STRIDE + nb2 + 1] = acc[m][nt][1];
                pp[(size_t)r1 * PART_STRIDE + nb2 + 1] = acc[m][nt][3];
            }
        }
        if (nb == 40 && tig == 0) {    // col 64 = 40 + 3*8 + 0
            pp[(size_t)r0 * PART_STRIDE + 64] = acc[m][3][0];
            pp[(size_t)r1 * PART_STRIDE + 64] = acc[m][3][2];
        }
    }

    // ---- fused final reduce: last CTA of this i-block does num/den + elu
    __threadfence();
    __syncthreads();
    if (t == 0) {
        int prev = atomicAdd(&g_cnt[ib], 1);
        s_last = (prev == NSPLIT - 1);
    }
    __syncthreads();
    if (s_last) {
        __threadfence();           // acquire side
#pragma unroll
        for (int rep = 0; rep < 8; rep++) {
            int w = t + 256 * rep;           // 0 .. 2047
            int il = w >> 4;                 // row 0..127
            int c4 = (w & 15) * 4;
            float4 num = make_float4(0.f, 0.f, 0.f, 0.f);
            float den = 0.f;
#pragma unroll
            for (int s = 0; s < NSPLIT; s++) {
                const float* q = &g_part[((size_t)s * NN + i0 + il) * PART_STRIDE];
                float4 v = *(const float4*)(q + c4);
                num.x += v.x; num.y += v.y; num.z += v.z; num.w += v.w;
                den += q[64];
            }
            float4 r;
            r.x = elu_f(num.x / den);
            r.y = elu_f(num.y / den);
            r.z = elu_f(num.z / den);
            r.w = elu_f(num.w / den);
            *(float4*)&out[(size_t)(i0 + il) * FOUT + c4] = r;
        }
        if (t == 0) {
            g_cnt[ib] = 0;                       // rearm for next replay
            if (ib == 0) g_m2key = 0u;           // rearm global max
        }
    }
}

// ---------------------------------------------------------------------------
extern "C" void kernel_launch(void* const* d_in, const int* in_sizes, int n_in,
                              void* d_out, int out_size)
{
    const float* h   = (const float*)d_in[0];
    const int*   adj = (const int*)d_in[1];
    const float* W   = (const float*)d_in[2];
    const float* a   = (const float*)d_in[3];
    float* out = (float*)d_out;

    cudaFuncSetAttribute(k_gat, cudaFuncAttributeMaxDynamicSharedMemorySize,
                         SMEM_TOTAL);

    k_gemm_wh<<<NN / 64, 256>>>(h, W, a);
    k_consts<<<NN / 256, 256>>>();
    k_gat<<<(NN / BM) * NSPLIT, 256, SMEM_TOTAL>>>(adj, out);
}

// round 15
// speedup vs baseline: 1.3338x; 1.3338x over previous
#include <cuda_runtime.h>
#include <cuda_fp16.h>
#include <math.h>
#include <stdint.h>

#define NN 8192
#define FIN 256
#define FOUT 64
#define LRALPHA 0.2f

#define BM 128
#define BK 64
#define NB 80               // B n-rows: 64 out + ones(64) + zeros(65..79)
#define ASTR 72             // A SMEM stride (halves)
#define BSTR 72             // B SMEM stride (halves)
#define NSPLIT 4
#define JCHUNK (NN / NSPLIT)        // 2048
#define NTILES (JCHUNK / BK)        // 32
#define PART_STRIDE 72

// ---- persistent scratch (no allocations allowed) ----
__device__ __align__(16) __half g_Wht[(size_t)NB * NN];   // transposed fp16 Wh + ones/zeros
__device__ __align__(16) float4 g_rowc[NN];  // (f1, exp(f1-m), exp(.2f1-m), 0)
__device__ __align__(16) float g_cpl[3 * NN]; // planar: [f2][exp(f2)][exp(.2f2)]
__device__ float g_f1[NN];
__device__ float g_f2[NN];
__device__ unsigned int g_m2key = 0u;        // reset at end of k_reduce (prev replay)
__device__ __align__(16) float g_part[(size_t)NSPLIT * NN * PART_STRIDE];

__device__ __forceinline__ float elu_f(float x) {
    return x > 0.f ? x : expm1f(x);
}
__device__ __forceinline__ unsigned int fkey(float x) {
    unsigned int b = __float_as_uint(x);
    return (b & 0x80000000u) ? ~b : (b | 0x80000000u);
}
__device__ __forceinline__ float fdecode(unsigned int k) {
    return __uint_as_float((k & 0x80000000u) ? (k & 0x7fffffffu) : ~k);
}
__device__ __forceinline__ void cp_async16(uint32_t smem_addr, const void* gptr) {
    asm volatile("cp.async.cg.shared.global [%0], [%1], 16;\n"
                 :: "r"(smem_addr), "l"(gptr));
}
__device__ __forceinline__ void cp_commit() {
    asm volatile("cp.async.commit_group;\n" ::: "memory");
}
__device__ __forceinline__ void cp_wait1() {
    asm volatile("cp.async.wait_group 1;\n" ::: "memory");
}
__device__ __forceinline__ void cp_wait0() {
    asm volatile("cp.async.wait_group 0;\n" ::: "memory");
}
__device__ __forceinline__ void ldsm_x4(uint32_t& r0, uint32_t& r1,
                                        uint32_t& r2, uint32_t& r3, uint32_t a) {
    asm volatile("ldmatrix.sync.aligned.m8n8.x4.shared.b16 {%0,%1,%2,%3}, [%4];"
                 : "=r"(r0), "=r"(r1), "=r"(r2), "=r"(r3) : "r"(a));
}
__device__ __forceinline__ void ldsm_x2(uint32_t& r0, uint32_t& r1, uint32_t a) {
    asm volatile("ldmatrix.sync.aligned.m8n8.x2.shared.b16 {%0,%1}, [%2];"
                 : "=r"(r0), "=r"(r1) : "r"(a));
}

// ---------------------------------------------------------------------------
// Kernel 1: Wh = h @ W (fp32), transposed fp16 store; fused f1/f2 + M2.
// SINGLE CHANGE vs R13: 32-row blocks, grid 256 (2 CTAs/SM, 16 warps) —
// the kernel is latency-bound (occ 12.5%, nothing saturated), not LDS-bound.
// Thread = (rs = t>>4: rows 2rs..2rs+1) x (cg = t&15: cols 4cg..4cg+3).
// ---------------------------------------------------------------------------
__global__ __launch_bounds__(256) void k_gemm_wh(
    const float* __restrict__ h, const float* __restrict__ W,
    const float* __restrict__ a)
{
    __shared__ float hs[32][68];
    __shared__ float wt2[64][68];
    __shared__ unsigned int smax;
    float* ts = &hs[0][0];         // alias: transpose staging [c][r], stride 33

    int t = threadIdx.x;
    int i0 = blockIdx.x * 32;
    int cg = t & 15;               // col-group: cols 4cg..4cg+3
    int rs = t >> 4;               // row-slot : rows 2rs..2rs+1

    if (t == 0) smax = 0u;

    float4 acc[2];
#pragma unroll
    for (int q = 0; q < 2; q++) acc[q] = make_float4(0.f, 0.f, 0.f, 0.f);

    for (int kt = 0; kt < FIN; kt += 64) {
        __syncthreads();
#pragma unroll
        for (int it = 0; it < 8; it++) {
            int l = t + 256 * it;            // 0..2047
            int r = l >> 6, c = l & 63;
            hs[r][c] = h[(size_t)(i0 + r) * FIN + kt + c];
        }
#pragma unroll
        for (int it = 0; it < 16; it++) {
            int l = t + 256 * it;            // 0..4095
            int r = l >> 6, c = l & 63;
            wt2[r][c] = W[(size_t)(kt + r) * FOUT + c];
        }
        __syncthreads();
#pragma unroll
        for (int k4 = 0; k4 < 16; k4++) {
            float4 w0 = *(const float4*)&wt2[k4 * 4 + 0][cg * 4];
            float4 w1 = *(const float4*)&wt2[k4 * 4 + 1][cg * 4];
            float4 w2 = *(const float4*)&wt2[k4 * 4 + 2][cg * 4];
            float4 w3 = *(const float4*)&wt2[k4 * 4 + 3][cg * 4];
#pragma unroll
            for (int q = 0; q < 2; q++) {
                float4 hv = *(const float4*)&hs[rs * 2 + q][k4 * 4];  // broadcast
                acc[q].x += hv.x * w0.x + hv.y * w1.x + hv.z * w2.x + hv.w * w3.x;
                acc[q].y += hv.x * w0.y + hv.y * w1.y + hv.z * w2.y + hv.w * w3.y;
                acc[q].z += hv.x * w0.z + hv.y * w1.z + hv.z * w2.z + hv.w * w3.z;
                acc[q].w += hv.x * w0.w + hv.y * w1.w + hv.z * w2.w + hv.w * w3.w;
            }
        }
    }

    // ---- fused f1/f2: per-row dots with a1/a2, reduce across the 16 cg lanes
    {
        float4 a1v = *(const float4*)&a[4 * cg];
        float4 a2v = *(const float4*)&a[64 + 4 * cg];
        float s1[2], s2[2];
#pragma unroll
        for (int q = 0; q < 2; q++) {
            s1[q] = acc[q].x * a1v.x + acc[q].y * a1v.y
                  + acc[q].z * a1v.z + acc[q].w * a1v.w;
            s2[q] = acc[q].x * a2v.x + acc[q].y * a2v.y
                  + acc[q].z * a2v.z + acc[q].w * a2v.w;
        }
#pragma unroll
        for (int o = 8; o > 0; o >>= 1) {
#pragma unroll
            for (int q = 0; q < 2; q++) {
                s1[q] += __shfl_xor_sync(0xffffffffu, s1[q], o);
                s2[q] += __shfl_xor_sync(0xffffffffu, s2[q], o);
            }
        }
        if (cg == 0) {
            float mm = -1e30f;
#pragma unroll
            for (int q = 0; q < 2; q++) {
                g_f1[i0 + rs * 2 + q] = s1[q];
                g_f2[i0 + rs * 2 + q] = s2[q];
                mm = fmaxf(mm, s2[q]);
            }
            atomicMax(&smax, fkey(mm));
        }
    }
    __syncthreads();               // hs free; smax complete
    if (t == 0) atomicMax(&g_m2key, smax);

    // ---- stage transpose ts[c][r] (stride 33), then fp16 write
#pragma unroll
    for (int q = 0; q < 2; q++) {
        ts[(4 * cg + 0) * 33 + rs * 2 + q] = acc[q].x;
        ts[(4 * cg + 1) * 33 + rs * 2 + q] = acc[q].y;
        ts[(4 * cg + 2) * 33 + rs * 2 + q] = acc[q].z;
        ts[(4 * cg + 3) * 33 + rs * 2 + q] = acc[q].w;
    }
    __syncthreads();
    {
        int c2 = t >> 2, q = t & 3;        // c2: col 0..63, q: 8-row chunk
        __half2 hx[4];
#pragma unroll
        for (int j = 0; j < 4; j++)
            hx[j] = __floats2half2_rn(ts[c2 * 33 + q * 8 + 2 * j],
                                      ts[c2 * 33 + q * 8 + 2 * j + 1]);
        *(float4*)&g_Wht[(size_t)c2 * NN + i0 + q * 8] = *(float4*)&hx[0];
    }
    // ones / zero rows 64..79 for this i-slice (2 halves per thread)
    {
        int rz = 64 + (t >> 4), ii = (t & 15) * 2;
        __half v = (rz == 64) ? __float2half(1.0f) : __float2half(0.0f);
        *(__half2*)&g_Wht[(size_t)rz * NN + i0 + ii] = __halves2half2(v, v);
    }
}

// ---------------------------------------------------------------------------
// Kernel 2: row constants (AoS) + column constants (planar).  (Unchanged.)
// ---------------------------------------------------------------------------
__global__ __launch_bounds__(256) void k_consts()
{
    int i = blockIdx.x * 256 + threadIdx.x;
    float M2 = fdecode(g_m2key);
    float f1 = g_f1[i], f2 = g_f2[i];
    float z = f1 + M2;
    float m = (z > 0.f) ? z : LRALPHA * z;
    g_rowc[i] = make_float4(f1, expf(f1 - m), expf(LRALPHA * f1 - m), 0.f);
    g_cpl[i]          = f2;
    g_cpl[NN + i]     = expf(f2);
    g_cpl[2 * NN + i] = expf(LRALPHA * f2);
}

// ---------------------------------------------------------------------------
// Kernel 3: fused masked-softmax attention partials — BYTE-IDENTICAL to the
// proven 82.7us R13 version (double-buffer, 3 syncs/tile, cp_wait1 lag-2).
// SMEM (bytes):
//   [0,     18432)  half  A[128][72]
//   [18432, 41472)  half  B[2][80][72]
//   [41472, 43008)  float colc[2][3][64]   (planar)
//   [43008, 45056)  float4 rowcs[128]
// ---------------------------------------------------------------------------
#define SM_A     0
#define SM_B     18432
#define SM_COLC  41472
#define SM_ROWC  43008
#define SMEM_TOTAL 45056
#define BBUF (NB * BSTR * 2)       // 11520

__global__ __launch_bounds__(256, 2) void k_gat(const int* __restrict__ adj)
{
    extern __shared__ __align__(16) char smem[];
    uint32_t sbase = (uint32_t)__cvta_generic_to_shared(smem);

    int t = threadIdx.x;
    int warp = t >> 5, lane = t & 31;
    int i0 = (blockIdx.x >> 2) * BM;
    int split = blockIdx.x & 3;
    int jstart = split * JCHUNK;

    // fixed row constants for the whole CTA
    if (t < 128) ((float4*)(smem + SM_ROWC))[t] = g_rowc[i0 + t];

    // w-gen mapping: warp -> rows 16w..16w+15; lane: rp = l>>4 row parity,
    // cq = l&15 -> cols 4cq..4cq+3.  Thread rows: wrow0 + rp + 2k, k=0..7.
    int wrow0 = warp * 16;
    int rp = lane >> 4;
    int cq = lane & 15;
    const int* aptr = adj + (size_t)(i0 + wrow0 + rp) * NN + 4 * cq;

    // MMA mapping
    int mb = (warp & 3) * 32;      // 32 rows (2 m-tiles)
    int nb = (warp >> 2) * 40;     // 40 cols (5 n-tiles)
    int g = lane >> 2, tig = lane & 3;

    // ldmatrix lane addresses
    uint32_t a_ad0 = sbase + SM_A +
        (uint32_t)(((mb + (lane & 15)) * ASTR + ((lane >> 4) << 3)) * 2);
    uint32_t a_ad1 = a_ad0 + 16 * ASTR * 2;
    uint32_t b_off_p = (uint32_t)(((nb + ((lane >> 4) << 3) + (lane & 7)) * BSTR
                                   + (((lane >> 3) & 1) << 3)) * 2);
    uint32_t b_off_2 = (uint32_t)(((nb + 32 + (lane & 7)) * BSTR
                                   + (((lane >> 3) & 1) << 3)) * 2);

    float acc[2][5][4];
#pragma unroll
    for (int m = 0; m < 2; m++)
#pragma unroll
        for (int n = 0; n < 5; n++)
#pragma unroll
            for (int x = 0; x < 4; x++) acc[m][n][x] = 0.f;

    // ---- prologue: B(0)+colc(0) cp.async into buf 0; adj(0) -> registers
    {
#pragma unroll
        for (int it = 0; it < 3; it++) {
            int l = t + 256 * it;
            if (l < 640) {
                int n = l >> 3, kc = l & 7;
                cp_async16(sbase + SM_B + (uint32_t)(n * (BSTR * 2) + kc * 16),
                           &g_Wht[(size_t)n * NN + jstart + kc * 8]);
            }
        }
        if (t < 48) {
            int p = t >> 4, x = t & 15;
            cp_async16(sbase + SM_COLC + (uint32_t)(p * 256 + x * 16),
                       &g_cpl[(size_t)p * NN + jstart + x * 4]);
        }
        cp_commit();
    }

    int4 av[8];
#pragma unroll
    for (int k = 0; k < 8; k++)
        av[k] = __ldcs((const int4*)(aptr + (size_t)(2 * k) * NN + jstart));

    for (int tt = 0; tt < NTILES; tt++) {
        int buf = tt & 1;
        int j0 = jstart + tt * BK;

        // 1. all warps done with MMA(tt-1) (reads B[buf^1]) before refill
        __syncthreads();

        // 2. issue B(tt+1)/colc(tt+1) into buf^1
        if (tt + 1 < NTILES) {
            int jn = j0 + BK;
            uint32_t bd = sbase + SM_B + (uint32_t)(buf ^ 1) * BBUF;
            uint32_t cd = sbase + SM_COLC + (uint32_t)(buf ^ 1) * 768;
#pragma unroll
            for (int it = 0; it < 3; it++) {
                int l = t + 256 * it;
                if (l < 640) {
                    int n = l >> 3, kc = l & 7;
                    cp_async16(bd + (uint32_t)(n * (BSTR * 2) + kc * 16),
                               &g_Wht[(size_t)n * NN + jn + kc * 8]);
                }
            }
            if (t < 48) {
                int p = t >> 4, x = t & 15;
                cp_async16(cd + (uint32_t)(p * 256 + x * 16),
                           &g_cpl[(size_t)p * NN + jn + x * 4]);
            }
            cp_commit();
            cp_wait1();   // B(tt)/colc(tt) complete; tt+1 in flight
        } else {
            cp_wait0();
        }

        // 3. visibility of B(tt)/colc(tt)
        __syncthreads();

        // 4. w-gen: registers(adj int4) + planar colc + rowc -> fp16 A[128][64]
        {
            const float* cp0 = (const float*)(smem + SM_COLC + buf * 768);
            float4 f2v = *(const float4*)(cp0 + 4 * cq);
            float4 yv  = *(const float4*)(cp0 + 64 + 4 * cq);
            float4 zv  = *(const float4*)(cp0 + 128 + 4 * cq);
            const float4* rw = (const float4*)(smem + SM_ROWC) + wrow0;
            __half* Ah = (__half*)(smem + SM_A);
#pragma unroll
            for (int k = 0; k < 8; k++) {
                int row = rp + 2 * k;
                float4 rc = rw[row];               // LDS 2-way broadcast
                int4 a4 = av[k];
                float w0 = ((rc.x + f2v.x) > 0.f) ? rc.y * yv.x : rc.z * zv.x;
                float w1 = ((rc.x + f2v.y) > 0.f) ? rc.y * yv.y : rc.z * zv.y;
                float w2 = ((rc.x + f2v.z) > 0.f) ? rc.y * yv.z : rc.z * zv.z;
                float w3 = ((rc.x + f2v.w) > 0.f) ? rc.y * yv.w : rc.z * zv.w;
                w0 = a4.x ? w0 : 0.f;
                w1 = a4.y ? w1 : 0.f;
                w2 = a4.z ? w2 : 0.f;
                w3 = a4.w ? w3 : 0.f;
                __half2 p0 = __floats2half2_rn(w0, w1);
                __half2 p1 = __floats2half2_rn(w2, w3);
                uint2 pk;
                pk.x = *(uint32_t*)&p0;
                pk.y = *(uint32_t*)&p1;
                *(uint2*)&Ah[(wrow0 + row) * ASTR + 4 * cq] = pk;   // STS.64
            }
        }

        // 5. stream adj(tt+1) into registers (flies over sync + MMA)
        if (tt + 1 < NTILES) {
            int jn = j0 + BK;
#pragma unroll
            for (int k = 0; k < 8; k++)
                av[k] = __ldcs((const int4*)(aptr + (size_t)(2 * k) * NN + jn));
        }

        // 6. A visible
        __syncthreads();

        // 7. MMA: 4 k-steps x (2 m-tiles x 5 n-tiles), ldmatrix fragments
        uint32_t b_base = sbase + SM_B + (uint32_t)buf * BBUF;
#pragma unroll
        for (int kt = 0; kt < 4; kt++) {
            uint32_t koff = (uint32_t)kt * 32;    // 16 halves
            uint32_t a0[4], a1[4], bb[10];
            ldsm_x4(a0[0], a0[1], a0[2], a0[3], a_ad0 + koff);
            ldsm_x4(a1[0], a1[1], a1[2], a1[3], a_ad1 + koff);
            ldsm_x4(bb[0], bb[1], bb[2], bb[3], b_base + b_off_p + koff);
            ldsm_x4(bb[4], bb[5], bb[6], bb[7],
                    b_base + b_off_p + 16 * BSTR * 2 + koff);
            ldsm_x2(bb[8], bb[9], b_base + b_off_2 + koff);
#pragma unroll
            for (int nt = 0; nt < 5; nt++) {
                uint32_t b0 = bb[2 * nt], b1 = bb[2 * nt + 1];
                asm volatile(
                    "mma.sync.aligned.m16n8k16.row.col.f32.f16.f16.f32 "
                    "{%0,%1,%2,%3}, {%4,%5,%6,%7}, {%8,%9}, {%0,%1,%2,%3};\n"
                    : "+f"(acc[0][nt][0]), "+f"(acc[0][nt][1]),
                      "+f"(acc[0][nt][2]), "+f"(acc[0][nt][3])
                    : "r"(a0[0]), "r"(a0[1]), "r"(a0[2]), "r"(a0[3]),
                      "r"(b0), "r"(b1));
                asm volatile(
                    "mma.sync.aligned.m16n8k16.row.col.f32.f16.f16.f32 "
                    "{%0,%1,%2,%3}, {%4,%5,%6,%7}, {%8,%9}, {%0,%1,%2,%3};\n"
                    : "+f"(acc[1][nt][0]), "+f"(acc[1][nt][1]),
                      "+f"(acc[1][nt][2]), "+f"(acc[1][nt][3])
                    : "r"(a1[0]), "r"(a1[1]), "r"(a1[2]), "r"(a1[3]),
                      "r"(b0), "r"(b1));
            }
        }
    }

    // ---- write partials: nums (cols 0..63) + den (logical col 64)
    float* pp = &g_part[((size_t)split * NN + i0) * PART_STRIDE];
#pragma unroll
    for (int m = 0; m < 2; m++) {
        int r0 = mb + m * 16 + g, r1 = r0 + 8;
#pragma unroll
        for (int nt = 0; nt < 5; nt++) {
            int nb2 = nb + nt * 8 + 2 * tig;
            if (nb2 < 64) {
                pp[(size_t)r0 * PART_STRIDE + nb2] = acc[m][nt][0];
                pp[(size_t)r1 * PART_STRIDE + nb2] = acc[m][nt][2];
            }
            if (nb2 + 1 < 64) {
                pp[(size_t)r0 * PART_STRIDE + nb2 + 1] = acc[m][nt][1];
                pp[(size_t)r1 * PART_STRIDE + nb2 + 1] = acc[m][nt][3];
            }
        }
        if (nb == 40 && tig == 0) {    // col 64 = 40 + 3*8 + 0
            pp[(size_t)r0 * PART_STRIDE + 64] = acc[m][3][0];
            pp[(size_t)r1 * PART_STRIDE + 64] = acc[m][3][2];
        }
    }
}

// ---------------------------------------------------------------------------
// Kernel 4: reduce partials across splits + elu + g_m2key reset (R13 version).
// ---------------------------------------------------------------------------
__global__ __launch_bounds__(256) void k_reduce(float* __restrict__ out)
{
    int idx = blockIdx.x * 256 + threadIdx.x;   // 0 .. NN*16
    int i = idx >> 4;
    int c4 = (idx & 15) * 4;

    float4 num = make_float4(0.f, 0.f, 0.f, 0.f);
    float den = 0.f;
#pragma unroll
    for (int s = 0; s < NSPLIT; s++) {
        const float* pp = &g_part[((size_t)s * NN + i) * PART_STRIDE];
        float4 v = *(const float4*)(pp + c4);
        num.x += v.x; num.y += v.y; num.z += v.z; num.w += v.w;
        den += pp[64];
    }
    float4 r;
    r.x = elu_f(num.x / den);
    r.y = elu_f(num.y / den);
    r.z = elu_f(num.z / den);
    r.w = elu_f(num.w / den);
    *(float4*)&out[(size_t)i * FOUT + c4] = r;

    if (blockIdx.x == 0 && threadIdx.x == 0) g_m2key = 0u;  // for next replay
}

// ---------------------------------------------------------------------------
extern "C" void kernel_launch(void* const* d_in, const int* in_sizes, int n_in,
                              void* d_out, int out_size)
{
    const float* h   = (const float*)d_in[0];
    const int*   adj = (const int*)d_in[1];
    const float* W   = (const float*)d_in[2];
    const float* a   = (const float*)d_in[3];
    float* out = (float*)d_out;

    cudaFuncSetAttribute(k_gat, cudaFuncAttributeMaxDynamicSharedMemorySize,
                         SMEM_TOTAL);

    k_gemm_wh<<<NN / 32, 256>>>(h, W, a);
    k_consts<<<NN / 256, 256>>>();
    k_gat<<<(NN / BM) * NSPLIT, 256, SMEM_TOTAL>>>(adj);
    k_reduce<<<NN * 16 / 256, 256>>>(out);
}